// round 2
// baseline (speedup 1.0000x reference)
#include <cuda_runtime.h>
#include <cuda_bf16.h>
#include <math.h>

// Row-normalize two [B=32, N=1024, N=1024] fp32 tensors:
//   out[b,i,:] = in[b,i,:] / sum(in[b,i,:]),  with 1/deg zeroed if non-finite.
// Output = concat(norm(adj0), norm(adj1)) in d_out.
//
// Strategy: pure HBM-bound, single pass. One warp per 1024-float row.
// Each lane: 8 independent float4 loads (MLP=8), lane-local sum,
// 5-step butterfly shuffle reduce, scale in registers, 8 float4 stores.
// No shared memory, no block barriers. Data touched exactly once.

static constexpr int ROWS_PER_TENSOR = 32 * 1024;           // 32768
static constexpr int TOTAL_ROWS      = 2 * ROWS_PER_TENSOR; // 65536
static constexpr int WARPS_PER_BLOCK = 8;
static constexpr int THREADS         = WARPS_PER_BLOCK * 32;

__global__ __launch_bounds__(THREADS, 8)
void normalizer_kernel(const float* __restrict__ adj0,
                       const float* __restrict__ adj1,
                       float* __restrict__ out)
{
    const int gwarp = (blockIdx.x * WARPS_PER_BLOCK) + (threadIdx.x >> 5);
    const int lane  = threadIdx.x & 31;

    // Select source tensor; rows 0..32767 -> adj0, 32768..65535 -> adj1.
    const bool second = (gwarp >= ROWS_PER_TENSOR);
    const float* src  = second ? adj1 : adj0;
    const long long local_row = second ? (long long)(gwarp - ROWS_PER_TENSOR)
                                       : (long long)gwarp;

    const float4* in = reinterpret_cast<const float4*>(src + local_row * 1024);
    float4*       o  = reinterpret_cast<float4*>(out + (long long)gwarp * 1024);

    // 8 independent vector loads per lane -> front-batched LDG.128, MLP=8.
    float4 v[8];
    float s = 0.0f;
#pragma unroll
    for (int i = 0; i < 8; i++) {
        v[i] = in[lane + i * 32];
        s += (v[i].x + v[i].y) + (v[i].z + v[i].w);
    }

    // Warp butterfly reduction of the row sum.
#pragma unroll
    for (int off = 16; off > 0; off >>= 1)
        s += __shfl_xor_sync(0xffffffffu, s, off);

    // inv = 1/degree, zeroed when non-finite (degree==0 or degree non-finite),
    // matching the reference's remove_nan_inf.
    float inv = 1.0f / s;
    if (!isfinite(inv)) inv = 0.0f;

    // Scale in registers, write back once.
#pragma unroll
    for (int i = 0; i < 8; i++) {
        float4 t = v[i];
        t.x *= inv; t.y *= inv; t.z *= inv; t.w *= inv;
        o[lane + i * 32] = t;
    }
}

extern "C" void kernel_launch(void* const* d_in, const int* in_sizes, int n_in,
                              void* d_out, int out_size)
{
    const float* adj0 = (const float*)d_in[0];
    const float* adj1 = (const float*)d_in[1];
    float* out = (float*)d_out;

    const int blocks = TOTAL_ROWS / WARPS_PER_BLOCK; // 8192, exact cover
    normalizer_kernel<<<blocks, THREADS>>>(adj0, adj1, out);
}

// round 5
// speedup vs baseline: 1.2195x; 1.2195x over previous
#include <cuda_runtime.h>
#include <cuda_bf16.h>
#include <math.h>

// Row-normalize two [B=32, N=1024, N=1024] fp32 tensors, single pass.
// out[b,i,:] = in[b,i,:] * inv(sum(in[b,i,:])), inv zeroed if non-finite.
// Output = concat(norm(adj0), norm(adj1)).
//
// R2 change vs R1 (97.7us, DRAM 71.7%):
//  - 2 rows per warp, all 16 LDG.128 front-batched -> 8KB in flight per warp,
//    halves the reduce/store bubble per byte of traffic.
//  - __ldcs / __stcs: data is single-touch, evict-first keeps L2 clean for
//    the write stream.
// Predicted: ~90us, DRAM ~78%.

static constexpr int ROWS_PER_TENSOR = 32 * 1024;            // 32768
static constexpr int TOTAL_ROWS      = 2 * ROWS_PER_TENSOR;  // 65536
static constexpr int ROWS_PER_WARP   = 2;
static constexpr int WARPS_PER_BLOCK = 8;
static constexpr int THREADS         = WARPS_PER_BLOCK * 32;
static constexpr int BLOCKS = TOTAL_ROWS / (ROWS_PER_WARP * WARPS_PER_BLOCK); // 4096

__device__ __forceinline__ float4 ldcs4(const float4* p) {
    return __ldcs(p);
}

__global__ __launch_bounds__(THREADS, 3)
void normalizer_kernel(const float* __restrict__ adj0,
                       const float* __restrict__ adj1,
                       float* __restrict__ out)
{
    const int gwarp = (blockIdx.x * WARPS_PER_BLOCK) + (threadIdx.x >> 5);
    const int lane  = threadIdx.x & 31;

    // This warp owns rows r0 = 2*gwarp and r0+1 (global row index across the
    // concatenated output). ROWS_PER_TENSOR is even, so both rows live in the
    // same source tensor.
    const int r0 = gwarp * ROWS_PER_WARP;
    const bool second = (r0 >= ROWS_PER_TENSOR);
    const float* src  = second ? adj1 : adj0;
    const long long lr0 = second ? (long long)(r0 - ROWS_PER_TENSOR)
                                 : (long long)r0;

    const float4* inA = reinterpret_cast<const float4*>(src + lr0 * 1024) + lane;
    const float4* inB = inA + (1024 / 4);
    float4* oA = reinterpret_cast<float4*>(out + (long long)r0 * 1024) + lane;
    float4* oB = oA + (1024 / 4);

    // Front-batch all 16 vector loads (8KB in flight per warp).
    float4 a[8], b[8];
#pragma unroll
    for (int i = 0; i < 8; i++) a[i] = ldcs4(inA + i * 32);
#pragma unroll
    for (int i = 0; i < 8; i++) b[i] = ldcs4(inB + i * 32);

    float s0 = 0.0f, s1 = 0.0f;
#pragma unroll
    for (int i = 0; i < 8; i++) {
        s0 += (a[i].x + a[i].y) + (a[i].z + a[i].w);
        s1 += (b[i].x + b[i].y) + (b[i].z + b[i].w);
    }

    // Two butterfly reductions, interleaved.
#pragma unroll
    for (int off = 16; off > 0; off >>= 1) {
        s0 += __shfl_xor_sync(0xffffffffu, s0, off);
        s1 += __shfl_xor_sync(0xffffffffu, s1, off);
    }

    float inv0 = 1.0f / s0;
    float inv1 = 1.0f / s1;
    if (!isfinite(inv0)) inv0 = 0.0f;
    if (!isfinite(inv1)) inv1 = 0.0f;

    // Scale and stream the stores out (single-touch -> evict-first).
#pragma unroll
    for (int i = 0; i < 8; i++) {
        float4 t = a[i];
        t.x *= inv0; t.y *= inv0; t.z *= inv0; t.w *= inv0;
        __stcs(oA + i * 32, t);
    }
#pragma unroll
    for (int i = 0; i < 8; i++) {
        float4 t = b[i];
        t.x *= inv1; t.y *= inv1; t.z *= inv1; t.w *= inv1;
        __stcs(oB + i * 32, t);
    }
}

extern "C" void kernel_launch(void* const* d_in, const int* in_sizes, int n_in,
                              void* d_out, int out_size)
{
    const float* adj0 = (const float*)d_in[0];
    const float* adj1 = (const float*)d_in[1];
    float* out = (float*)d_out;

    normalizer_kernel<<<BLOCKS, THREADS>>>(adj0, adj1, out);
}